// round 2
// baseline (speedup 1.0000x reference)
#include <cuda_runtime.h>
#include <math.h>

#define NUM_E 640000
#define NUM_N 20000
#define NUM_H 8

// Scratch (allocation-free rule: __device__ globals)
__device__ float        g_raw[NUM_E * NUM_H];     // raw leaky-relu scores
__device__ float        g_tscore[NUM_N * NUM_H];  // per-(node,head) x_e dot w[:,16:]
__device__ unsigned int g_segmax[NUM_N * NUM_H];  // ordered-uint encoded float max
__device__ float        g_segsum[NUM_N * NUM_H];

// Ordered-uint encoding so unsigned atomicMax == float max
__device__ __forceinline__ unsigned enc_f(float f) {
    unsigned u = __float_as_uint(f);
    return (u & 0x80000000u) ? ~u : (u | 0x80000000u);
}
__device__ __forceinline__ float dec_f(unsigned u) {
    return (u & 0x80000000u) ? __uint_as_float(u ^ 0x80000000u)
                             : __uint_as_float(~u);
}

// ---------------------------------------------------------------------------
// K0: init segment accumulators
__global__ void k_init() {
    int i = blockIdx.x * blockDim.x + threadIdx.x;
    if (i < NUM_N * NUM_H) {
        g_segmax[i] = enc_f(-INFINITY);
        g_segsum[i] = 0.0f;
    }
}

// ---------------------------------------------------------------------------
// K1: per-node target scores. One warp per node. lane -> (head = lane>>2,
// quarter = lane&3), each lane handles 4 consecutive floats (float4).
__global__ void k_tscore(const float* __restrict__ x_e,
                         const float* __restrict__ weight) {
    int gtid = blockIdx.x * blockDim.x + threadIdx.x;
    int node = gtid >> 5;
    int lane = gtid & 31;
    if (node >= NUM_N) return;

    float4 x4 = reinterpret_cast<const float4*>(x_e)[node * 32 + lane];
    int h = lane >> 2, q = lane & 3;
    // weight row = 32 floats = 8 float4; x_t part is second half (offset 4)
    float4 w4 = reinterpret_cast<const float4*>(weight)[h * 8 + 4 + q];
    float p = x4.x * w4.x + x4.y * w4.y + x4.z * w4.z + x4.w * w4.w;
    p += __shfl_xor_sync(0xffffffffu, p, 1);
    p += __shfl_xor_sync(0xffffffffu, p, 2);
    if (q == 0) g_tscore[node * NUM_H + h] = p;
}

// ---------------------------------------------------------------------------
// K2: fused message copy-out + per-(edge,head) dot + LeakyReLU + atomicMax.
// One warp per edge (128 floats = 32 float4).
__global__ void k_edge(const float* __restrict__ message,
                       const int* __restrict__ target,
                       const float* __restrict__ weight,
                       float* __restrict__ out_msg) {
    int gtid = blockIdx.x * blockDim.x + threadIdx.x;
    int e    = gtid >> 5;
    int lane = gtid & 31;
    if (e >= NUM_E) return;

    float4 m4 = reinterpret_cast<const float4*>(message)[e * 32 + lane];
    reinterpret_cast<float4*>(out_msg)[e * 32 + lane] = m4;  // output copy

    int h = lane >> 2, q = lane & 3;
    float4 w4 = reinterpret_cast<const float4*>(weight)[h * 8 + q];  // msg half
    float p = m4.x * w4.x + m4.y * w4.y + m4.z * w4.z + m4.w * w4.w;
    p += __shfl_xor_sync(0xffffffffu, p, 1);
    p += __shfl_xor_sync(0xffffffffu, p, 2);

    if (q == 0) {
        int t = target[e];
        float s = p + g_tscore[t * NUM_H + h];
        s = (s >= 0.0f) ? s : 0.01f * s;          // LeakyReLU
        g_raw[e * NUM_H + h] = s;
        atomicMax(&g_segmax[t * NUM_H + h], enc_f(s));
    }
}

// ---------------------------------------------------------------------------
// K3: exp(raw - segmax) -> alpha slot; atomicAdd segment sum.
__global__ void k_exp(const int* __restrict__ target,
                      float* __restrict__ out_alpha) {
    int idx = blockIdx.x * blockDim.x + threadIdx.x;
    if (idx >= NUM_E * NUM_H) return;
    int e = idx >> 3, h = idx & 7;
    int t = target[e];
    float mx = dec_f(g_segmax[t * NUM_H + h]);
    float ex = expf(g_raw[idx] - mx);
    out_alpha[idx] = ex;
    atomicAdd(&g_segsum[t * NUM_H + h], ex);
}

// ---------------------------------------------------------------------------
// K4: normalize in place.
__global__ void k_norm(const int* __restrict__ target,
                       float* __restrict__ out_alpha) {
    int idx = blockIdx.x * blockDim.x + threadIdx.x;
    if (idx >= NUM_E * NUM_H) return;
    int e = idx >> 3, h = idx & 7;
    int t = target[e];
    out_alpha[idx] = out_alpha[idx] / (g_segsum[t * NUM_H + h] + 1e-16f);
}

// ---------------------------------------------------------------------------
extern "C" void kernel_launch(void* const* d_in, const int* in_sizes, int n_in,
                              void* d_out, int out_size) {
    const int*   edge_index = (const int*)d_in[0];    // (2, E) int32
    const float* message    = (const float*)d_in[1];  // (E, 128)
    const float* x_e        = (const float*)d_in[2];  // (N, 128)
    const float* weight     = (const float*)d_in[3];  // (8, 32)

    const int* target = edge_index + NUM_E;  // row 1

    float* out_msg   = (float*)d_out;                  // E*128 floats
    float* out_alpha = out_msg + (size_t)NUM_E * 128;  // E*8 floats

    const int TPB = 256;

    k_init<<<(NUM_N * NUM_H + TPB - 1) / TPB, TPB>>>();
    k_tscore<<<(NUM_N * 32 + TPB - 1) / TPB, TPB>>>(x_e, weight);
    k_edge<<<(NUM_E * 32 + TPB - 1) / TPB, TPB>>>(message, target, weight, out_msg);
    k_exp<<<(NUM_E * NUM_H + TPB - 1) / TPB, TPB>>>(target, out_alpha);
    k_norm<<<(NUM_E * NUM_H + TPB - 1) / TPB, TPB>>>(target, out_alpha);
}

// round 3
// speedup vs baseline: 1.0805x; 1.0805x over previous
#include <cuda_runtime.h>
#include <math.h>

#define NUM_E 640000
#define NUM_N 20000
#define NUM_H 8

// Scratch (allocation-free rule: __device__ globals)
__device__ float g_tscore[NUM_N * NUM_H];  // per-(node,head) x_e . w[h,16:]
__device__ float g_segsum[NUM_N * NUM_H];  // sum of exp per (node,head)

// ---------------------------------------------------------------------------
// K1: per-node target scores + zero segsum. One warp per node.
// lane -> (head = lane>>2, quarter = lane&3), each lane covers 4 floats.
__global__ void k_tscore(const float* __restrict__ x_e,
                         const float* __restrict__ weight) {
    int gtid = blockIdx.x * blockDim.x + threadIdx.x;
    int node = gtid >> 5;
    int lane = gtid & 31;
    if (node >= NUM_N) return;

    float4 x4 = reinterpret_cast<const float4*>(x_e)[node * 32 + lane];
    int h = lane >> 2, q = lane & 3;
    // weight row = 32 floats = 8 float4; x_t part is the second half (offset 4)
    float4 w4 = reinterpret_cast<const float4*>(weight)[h * 8 + 4 + q];
    float p = x4.x * w4.x + x4.y * w4.y + x4.z * w4.z + x4.w * w4.w;
    p += __shfl_xor_sync(0xffffffffu, p, 1);
    p += __shfl_xor_sync(0xffffffffu, p, 2);
    if (q == 0) {
        g_tscore[node * NUM_H + h] = p;
        g_segsum[node * NUM_H + h] = 0.0f;
    }
}

// ---------------------------------------------------------------------------
// K2: fused message copy-out + per-(edge,head) dot + LeakyReLU + exp +
// alpha numerator store + segment-sum atomicAdd. One warp per edge.
__global__ void k_edge(const float* __restrict__ message,
                       const int* __restrict__ target,
                       const float* __restrict__ weight,
                       float* __restrict__ out_msg,
                       float* __restrict__ out_alpha) {
    int gtid = blockIdx.x * blockDim.x + threadIdx.x;
    int e    = gtid >> 5;
    int lane = gtid & 31;
    if (e >= NUM_E) return;

    float4 m4 = reinterpret_cast<const float4*>(message)[e * 32 + lane];
    reinterpret_cast<float4*>(out_msg)[e * 32 + lane] = m4;  // output copy

    int h = lane >> 2, q = lane & 3;
    float4 w4 = reinterpret_cast<const float4*>(weight)[h * 8 + q];  // msg half
    float p = m4.x * w4.x + m4.y * w4.y + m4.z * w4.z + m4.w * w4.w;
    p += __shfl_xor_sync(0xffffffffu, p, 1);
    p += __shfl_xor_sync(0xffffffffu, p, 2);

    if (q == 0) {
        int t = target[e];
        float s = p + g_tscore[t * NUM_H + h];
        s = (s >= 0.0f) ? s : 0.01f * s;          // LeakyReLU
        float ex = expf(s);                       // no max-shift (safe range)
        out_alpha[e * NUM_H + h] = ex;
        atomicAdd(&g_segsum[t * NUM_H + h], ex);
    }
}

// ---------------------------------------------------------------------------
// K3: normalize alpha in place.
__global__ void k_norm(const int* __restrict__ target,
                       float* __restrict__ out_alpha) {
    int idx = blockIdx.x * blockDim.x + threadIdx.x;
    if (idx >= NUM_E * NUM_H) return;
    int e = idx >> 3, h = idx & 7;
    int t = target[e];
    out_alpha[idx] = out_alpha[idx] / (g_segsum[t * NUM_H + h] + 1e-16f);
}

// ---------------------------------------------------------------------------
extern "C" void kernel_launch(void* const* d_in, const int* in_sizes, int n_in,
                              void* d_out, int out_size) {
    const int*   edge_index = (const int*)d_in[0];    // (2, E) int32
    const float* message    = (const float*)d_in[1];  // (E, 128)
    const float* x_e        = (const float*)d_in[2];  // (N, 128)
    const float* weight     = (const float*)d_in[3];  // (8, 32)

    const int* target = edge_index + NUM_E;  // row 1

    float* out_msg   = (float*)d_out;                  // E*128 floats
    float* out_alpha = out_msg + (size_t)NUM_E * 128;  // E*8 floats

    const int TPB = 256;

    k_tscore<<<(NUM_N * 32 + TPB - 1) / TPB, TPB>>>(x_e, weight);
    k_edge<<<(NUM_E * 32 + TPB - 1) / TPB, TPB>>>(message, target, weight,
                                                  out_msg, out_alpha);
    k_norm<<<(NUM_E * NUM_H + TPB - 1) / TPB, TPB>>>(target, out_alpha);
}

// round 4
// speedup vs baseline: 1.3929x; 1.2892x over previous
#include <cuda_runtime.h>
#include <math.h>

#define NUM_E 640000
#define NUM_N 20000
#define NUM_H 8

// Scratch (allocation-free rule: __device__ globals)
__device__ __align__(16) float g_tscore[NUM_N * NUM_H];  // x_e[t] . w[h,16:]
__device__ __align__(16) float g_segsum[NUM_N * NUM_H];  // sum(exp) then recip

// ---------------------------------------------------------------------------
// K1: per-node target scores + zero segsum. One warp per node.
__global__ void k_tscore(const float* __restrict__ x_e,
                         const float* __restrict__ weight) {
    int gtid = blockIdx.x * blockDim.x + threadIdx.x;
    int node = gtid >> 5;
    int lane = gtid & 31;
    if (node >= NUM_N) return;

    float4 x4 = reinterpret_cast<const float4*>(x_e)[node * 32 + lane];
    int h = lane >> 2, q = lane & 3;
    float4 w4 = reinterpret_cast<const float4*>(weight)[h * 8 + 4 + q];
    float p = x4.x * w4.x + x4.y * w4.y + x4.z * w4.z + x4.w * w4.w;
    p += __shfl_xor_sync(0xffffffffu, p, 1);
    p += __shfl_xor_sync(0xffffffffu, p, 2);
    if (q == 0) {
        g_tscore[node * NUM_H + h] = p;
        g_segsum[node * NUM_H + h] = 0.0f;
    }
}

// ---------------------------------------------------------------------------
// K2: fused copy + dot + LeakyReLU + exp + alpha numerator + segsum atomic.
// One warp per 4 edges (MLP=4 float4 loads per thread).
#define EDGES_PER_WARP 4
__global__ void k_edge(const float* __restrict__ message,
                       const int* __restrict__ target,
                       const float* __restrict__ weight,
                       float* __restrict__ out_msg,
                       float* __restrict__ out_alpha) {
    int gtid = blockIdx.x * blockDim.x + threadIdx.x;
    int warp = gtid >> 5;
    int lane = gtid & 31;
    int e0 = warp * EDGES_PER_WARP;
    if (e0 >= NUM_E) return;

    const float4* msg4 = reinterpret_cast<const float4*>(message);
    float4*       out4 = reinterpret_cast<float4*>(out_msg);

    float4 m[EDGES_PER_WARP];
#pragma unroll
    for (int i = 0; i < EDGES_PER_WARP; i++)
        m[i] = __ldcs(&msg4[(size_t)(e0 + i) * 32 + lane]);   // streaming read
#pragma unroll
    for (int i = 0; i < EDGES_PER_WARP; i++)
        __stcs(&out4[(size_t)(e0 + i) * 32 + lane], m[i]);    // streaming write

    int h = lane >> 2, q = lane & 3;
    float4 w4 = reinterpret_cast<const float4*>(weight)[h * 8 + q];  // msg half

#pragma unroll
    for (int i = 0; i < EDGES_PER_WARP; i++) {
        float p = m[i].x * w4.x + m[i].y * w4.y + m[i].z * w4.z + m[i].w * w4.w;
        p += __shfl_xor_sync(0xffffffffu, p, 1);
        p += __shfl_xor_sync(0xffffffffu, p, 2);
        if (q == 0) {
            int e = e0 + i;
            int t = target[e];
            float s = p + g_tscore[t * NUM_H + h];
            s = (s >= 0.0f) ? s : 0.01f * s;          // LeakyReLU
            float ex = __expf(s);                     // no max-shift (safe)
            out_alpha[e * NUM_H + h] = ex;
            atomicAdd(&g_segsum[t * NUM_H + h], ex);
        }
    }
}

// ---------------------------------------------------------------------------
// K2.5: reciprocal of segment sums (turns k_norm divisions into multiplies)
__global__ void k_recip() {
    int i = blockIdx.x * blockDim.x + threadIdx.x;
    if (i < NUM_N * NUM_H)
        g_segsum[i] = 1.0f / (g_segsum[i] + 1e-16f);
}

// ---------------------------------------------------------------------------
// K3: normalize alpha. One thread per edge, vectorized float4.
__global__ void k_norm(const int* __restrict__ target,
                       float* __restrict__ out_alpha) {
    int e = blockIdx.x * blockDim.x + threadIdx.x;
    if (e >= NUM_E) return;
    int t = target[e];

    const float4* rs4 = reinterpret_cast<const float4*>(g_segsum);
    float4 r0 = rs4[t * 2 + 0];
    float4 r1 = rs4[t * 2 + 1];

    float4* a4 = reinterpret_cast<float4*>(out_alpha);
    float4 a0 = a4[e * 2 + 0];
    float4 a1 = a4[e * 2 + 1];

    a0.x *= r0.x; a0.y *= r0.y; a0.z *= r0.z; a0.w *= r0.w;
    a1.x *= r1.x; a1.y *= r1.y; a1.z *= r1.z; a1.w *= r1.w;

    a4[e * 2 + 0] = a0;
    a4[e * 2 + 1] = a1;
}

// ---------------------------------------------------------------------------
extern "C" void kernel_launch(void* const* d_in, const int* in_sizes, int n_in,
                              void* d_out, int out_size) {
    const int*   edge_index = (const int*)d_in[0];    // (2, E) int32
    const float* message    = (const float*)d_in[1];  // (E, 128)
    const float* x_e        = (const float*)d_in[2];  // (N, 128)
    const float* weight     = (const float*)d_in[3];  // (8, 32)

    const int* target = edge_index + NUM_E;  // row 1

    float* out_msg   = (float*)d_out;                  // E*128 floats
    float* out_alpha = out_msg + (size_t)NUM_E * 128;  // E*8 floats

    const int TPB = 256;

    k_tscore<<<(NUM_N * 32 + TPB - 1) / TPB, TPB>>>(x_e, weight);

    int warps_needed = NUM_E / EDGES_PER_WARP;           // 160000
    int blocks = (warps_needed * 32 + TPB - 1) / TPB;    // 20000
    k_edge<<<blocks, TPB>>>(message, target, weight, out_msg, out_alpha);

    k_recip<<<(NUM_N * NUM_H + TPB - 1) / TPB, TPB>>>();
    k_norm<<<(NUM_E + TPB - 1) / TPB, TPB>>>(target, out_alpha);
}